// round 7
// baseline (speedup 1.0000x reference)
#include <cuda_runtime.h>
#include <cstddef>

// ---- problem constants ----
#define HH 384
#define WW 384
#define NPIX (HH*WW)          // 147456
#define BB 4
#define MM 192
#define NT 512
#define TILE_W 64
#define TILE_H 64
#define TILES_X (WW/TILE_W)            // 6
#define TILES_Y (HH/TILE_H)            // 6
#define NCHUNK (TILES_X*TILES_Y)       // 36
#define NBLK1 (BB*NCHUNK)              // 144
#define NBLK2 ((BB*MM)/16)             // 48 (16 warps/block, 1 warp per (b,j))
#define TOTBLK (NBLK1+NBLK2)           // 192 -> ONE wave @ 2 CTAs/SM on 148 SMs
#define NWARP (NT/32)                  // 16
#define EPSF 1e-6f
#define MAX_DISTF 543.0580079975699f   // sqrt(384^2+384^2)
#define EPS_OVER_MAX 1.8414263e-9f     // 1e-6 / MAX_DIST
#define C2MIN 0.999999f
#define BIGF 3.4e38f

// ---- scratch (static device globals; g_sem reset by finalizer) ----
__device__ float    g_t1part[NBLK1];
__device__ float    g_ppart [NBLK1];
__device__ float    g_jval  [BB*MM];
__device__ unsigned g_sem;

// ---- packed f32x2 helpers ----
__device__ __forceinline__ unsigned long long pk2(float a, float b) {
    unsigned long long r;
    asm("mov.b64 %0, {%1, %2};" : "=l"(r) : "f"(a), "f"(b));
    return r;
}
__device__ __forceinline__ void upk2(float& a, float& b, unsigned long long v) {
    asm("mov.b64 {%0, %1}, %2;" : "=f"(a), "=f"(b) : "l"(v));
}
__device__ __forceinline__ unsigned long long addx2(unsigned long long a, unsigned long long b) {
    unsigned long long r;
    asm("add.rn.f32x2 %0, %1, %2;" : "=l"(r) : "l"(a), "l"(b));
    return r;
}
__device__ __forceinline__ unsigned long long fmax2(unsigned long long a, unsigned long long b,
                                                    unsigned long long c) {
    unsigned long long r;
    asm("fma.rn.f32x2 %0, %1, %2, %3;" : "=l"(r) : "l"(a), "l"(b), "l"(c));
    return r;
}

__global__ __launch_bounds__(NT, 2)
void whd_all(const float* __restrict__ pm,
             const float* __restrict__ gt,
             const float* __restrict__ osz,
             float* __restrict__ out)
{
    __shared__ float              s_gxs[MM];   // -gx of candidates
    __shared__ unsigned long long s_gy2[MM];   // (-gy,-gy) packed
    __shared__ float s_red[NWARP*2];
    __shared__ float s_t1[BB];
    __shared__ int   s_n;
    __shared__ bool  s_last;

    const int tid  = threadIdx.x;
    const int lane = tid & 31;
    const int wid  = tid >> 5;
    const int bid  = blockIdx.x;

    if (tid == 0) s_n = 0;

    if (bid < NBLK2) {
        // ==================== term2 role: one warp per (b,j) ====================
        const int wg = bid * NWARP + wid;          // 0..767
        const int b  = wg / MM;
        const int j  = wg - b * MM;

        const float fy = osz[2*b+0] * (1.0f/(float)HH);
        const float fx = osz[2*b+1] * (1.0f/(float)WW);
        const float grow = gt[((size_t)b*MM + j)*2 + 0];
        const float gcol = gt[((size_t)b*MM + j)*2 + 1];
        const float* pmb = pm + (size_t)b * NPIX;

        const int cx = (int)gcol;
        const int cy = (int)grow;

        float U;
        int r = 8;
        for (;;) {
            int x0 = cx - r, x1 = cx + r, y0 = cy - r, y1 = cy + r;
            const bool clx0 = (x0 <= 0), clx1 = (x1 >= WW-1);
            const bool cly0 = (y0 <= 0), cly1 = (y1 >= HH-1);
            x0 = max(x0, 0); y0 = max(y0, 0);
            x1 = min(x1, WW-1); y1 = min(y1, HH-1);
            const int wnd = x1 - x0 + 1;
            const int cnt = wnd * (y1 - y0 + 1);

            float kmin = BIGF;
            for (int idx = lane; idx < cnt; idx += 32) {
                int q  = idx / wnd;
                int px = x0 + (idx - q*wnd);
                int py = y0 + q;
                float p  = pmb[py*WW + px];
                float dx = ((float)px - gcol) * fx;
                float dy = ((float)py - grow) * fy;
                float d2 = fmaf(dx, dx, dy*dy);
                float pp = p*p;
                float c  = __fdividef(1.0f, pp*pp + EPS_OVER_MAX);
                kmin = fminf(kmin, d2 * (c*c));
            }
            unsigned u = __reduce_min_sync(0xffffffffu, __float_as_uint(kmin));
            U = __uint_as_float(u);

            if (clx0 && clx1 && cly0 && cly1) break;   // full image: exact

            const float GBIG = 1.0e18f;
            float gxl = clx0 ? GBIG : (gcol - (float)x0 + 1.0f) * fx;
            float gxh = clx1 ? GBIG : ((float)x1 + 1.0f - gcol) * fx;
            float gyl = cly0 ? GBIG : (grow - (float)y0 + 1.0f) * fy;
            float gyh = cly1 ? GBIG : ((float)y1 + 1.0f - grow) * fy;
            float G = fminf(fminf(gxl, gxh), fminf(gyl, gyh));
            if (U <= G*G*C2MIN) break;                 // exactness certified
            r <<= 1;
        }
        if (lane == 0)
            g_jval[wg] = fminf(sqrtf(U), MAX_DISTF);
    } else {
        // ==================== term1 role: one 64x64 pixel tile ====================
        const int tb    = bid - NBLK2;             // 0..143
        const int b     = tb / NCHUNK;
        const int chunk = tb - b * NCHUNK;
        const int tile_x = chunk % TILES_X;
        const int tile_y = chunk / TILES_X;

        const float fy = osz[2*b+0] * (1.0f/(float)HH);
        const float fx = osz[2*b+1] * (1.0f/(float)WW);
        const float* pmb = pm + (size_t)b * NPIX;

        const int col0 = tile_x * TILE_W;
        const int row0 = tile_y * TILE_H;
        const int colg = col0 + (tid & 63);
        const int rowb = row0 + (tid >> 6);        // rows rowb + 8k, k=0..7

        // issue pixel loads early (overlap with phase-0 cull)
        float pv[8];
#pragma unroll
        for (int k = 0; k < 8; ++k)
            pv[k] = pmb[(rowb + 8*k)*WW + colg];

        const float xn = (float)colg * fx;         // shared across 8 px of this thread
        unsigned long long nyp[4];
#pragma unroll
        for (int k = 0; k < 4; ++k)
            nyp[k] = pk2((float)(rowb + 16*k) * fy, (float)(rowb + 16*k + 8) * fy);

        // ---- phase 0: exact candidate culling (triangle inequality) ----
        const float cxn = ((float)col0 + 31.5f) * fx;
        const float cyn = ((float)row0 + 31.5f) * fy;
        const float hx = 31.5f * fx, hy = 31.5f * fy;
        const float Dh = sqrtf(hx*hx + hy*hy);     // tile half-diagonal (normalized)

        float dc = BIGF, gxn = 0.f, gyn = 0.f;
        if (tid < MM) {
            gyn = gt[((size_t)b*MM + tid)*2 + 0] * fy;
            gxn = gt[((size_t)b*MM + tid)*2 + 1] * fx;
            float ax = gxn - cxn, ay = gyn - cyn;
            dc = sqrtf(fmaf(ax, ax, ay*ay));
        }
        unsigned wm = __reduce_min_sync(0xffffffffu, __float_as_uint(dc));
        if (lane == 0) s_red[wid] = __uint_as_float(wm);
        __syncthreads();
        float Uc = fminf(fminf(fminf(s_red[0], s_red[1]), fminf(s_red[2], s_red[3])),
                         fminf(s_red[4], s_red[5]));
        // point j can be some tile pixel's argmin only if dc <= Uc + 2*Dh (+ slack)
        float thr = Uc + 2.0f*Dh + 1e-2f;
        if (tid < MM && dc <= thr) {
            int slot = atomicAdd(&s_n, 1);
            s_gxs[slot] = -gxn;
            s_gy2[slot] = pk2(-gyn, -gyn);
        }
        __syncthreads();
        const int ncand = s_n;

        // ---- hot loop over candidates only ----
        unsigned long long dmn[4] = {pk2(BIGF,BIGF), pk2(BIGF,BIGF),
                                     pk2(BIGF,BIGF), pk2(BIGF,BIGF)};
        float d2min[8];
        {
#pragma unroll 2
            for (int jj = 0; jj < ncand; ++jj) {
                float gxs = s_gxs[jj];                 // LDS broadcast
                unsigned long long gy2 = s_gy2[jj];
                float dx  = xn + gxs;
                float dxx = dx * dx;
                unsigned long long dxx2 = pk2(dxx, dxx);
#pragma unroll
                for (int k = 0; k < 4; ++k) {
                    unsigned long long dya = addx2(nyp[k], gy2);
                    unsigned long long d2a = fmax2(dya, dya, dxx2);
                    float a, bx, c0, c1;
                    upk2(a, bx, d2a);
                    upk2(c0, c1, dmn[k]);
                    dmn[k] = pk2(fminf(c0, a), fminf(c1, bx));
                }
            }
#pragma unroll
            for (int k = 0; k < 4; ++k)
                upk2(d2min[2*k], d2min[2*k+1], dmn[k]);
        }

        // ---- term1 partial: sum p*sqrt(min d2), sum p ----
        float t1 = 0.f, ps = 0.f;
#pragma unroll
        for (int k = 0; k < 8; ++k) {
            // d2min index order: k-th pair holds rows rowb+16k and rowb+16k+8
            int idx = (k >> 1) * 2 + (k & 1);
            t1 += pv[k] * 0.f + 0.f; // placeholder removed below
        }
        // direct accumulation (pairs map: dmn[k] = rows rowb+16k, rowb+16k+8
        //                      pv index:   rows rowb+8m -> m = 2k (+0) and 2k+1 (+8))
        t1 = 0.f; ps = 0.f;
#pragma unroll
        for (int k = 0; k < 4; ++k) {
            t1 += pv[2*k]   * sqrtf(d2min[2*k]);
            t1 += pv[2*k+1] * sqrtf(d2min[2*k+1]);
            ps += pv[2*k] + pv[2*k+1];
        }
#pragma unroll
        for (int off = 16; off > 0; off >>= 1) {
            t1 += __shfl_down_sync(0xffffffffu, t1, off);
            ps += __shfl_down_sync(0xffffffffu, ps, off);
        }
        __syncthreads();   // protect s_red reuse
        if (lane == 0) { s_red[wid] = t1; s_red[NWARP+wid] = ps; }
        __syncthreads();
        if (tid == 0) {
            float a = 0.f, c2 = 0.f;
#pragma unroll
            for (int w = 0; w < NWARP; ++w) { a += s_red[w]; c2 += s_red[NWARP+w]; }
            g_t1part[tb] = a;
            g_ppart [tb] = c2;
        }
    }

    // ==================== common tail: last-block finalize ====================
    __threadfence();
    __syncthreads();
    if (tid == 0) s_last = (atomicAdd(&g_sem, 1u) == (unsigned)(TOTBLK - 1));
    __syncthreads();
    if (!s_last) return;

    // term2 total: fixed-order deterministic sum of 768 values
    float acc = 0.f;
#pragma unroll
    for (int t = tid; t < BB*MM; t += NT) acc += g_jval[t];
#pragma unroll
    for (int off = 16; off > 0; off >>= 1)
        acc += __shfl_down_sync(0xffffffffu, acc, off);

    // term1 ratios: warps 0..3, one image each (fixed-order)
    if (wid < BB) {
        float nu = 0.f, de = 0.f;
        for (int c = lane; c < NCHUNK; c += 32) {
            nu += g_t1part[wid*NCHUNK + c];
            de += g_ppart [wid*NCHUNK + c];
        }
#pragma unroll
        for (int off = 16; off > 0; off >>= 1) {
            nu += __shfl_down_sync(0xffffffffu, nu, off);
            de += __shfl_down_sync(0xffffffffu, de, off);
        }
        if (lane == 0) s_t1[wid] = nu / (de + EPSF);
    }
    if (lane == 0) s_red[wid] = acc;
    __syncthreads();

    if (tid == 0) {
        float t2 = 0.f;
#pragma unroll
        for (int w = 0; w < NWARP; ++w) t2 += s_red[w];
        float t1sum = 0.f;
#pragma unroll
        for (int bb = 0; bb < BB; ++bb) t1sum += s_t1[bb];
        out[0] = t1sum * (1.0f/(float)BB) + t2 * (1.0f/(float)(BB*MM));
        g_sem = 0u;                                // reset for next replay
    }
}

extern "C" void kernel_launch(void* const* d_in, const int* in_sizes, int n_in,
                              void* d_out, int out_size)
{
    const float* pm  = nullptr;
    const float* gt  = nullptr;
    const float* osz = nullptr;
    for (int i = 0; i < n_in; ++i) {
        if      (in_sizes[i] == BB*NPIX) pm  = (const float*)d_in[i];
        else if (in_sizes[i] == BB*MM*2) gt  = (const float*)d_in[i];
        else if (in_sizes[i] == BB*2)    osz = (const float*)d_in[i];
    }
    whd_all<<<TOTBLK, NT>>>(pm, gt, osz, (float*)d_out);
    (void)out_size;
}